// round 8
// baseline (speedup 1.0000x reference)
#include <cuda_runtime.h>
#include <math.h>
#include <stdint.h>

#define BB   2
#define SS   2048
#define DMODEL 1024
#define HQ   16
#define HKV  4
#define DK   64
#define KVD  256   // HKV*DK

// ---------------- scratch (no allocations allowed) ----------------
__device__ float g_Q[BB*SS*DMODEL];
__device__ float g_K[BB*SS*KVD];
__device__ float g_V[BB*SS*KVD];
__device__ float g_attn[BB*SS*DMODEL];
__device__ float g_cos[SS*(DK/2)];
__device__ float g_sin[SS*(DK/2)];

// ---------------- helpers ----------------
__device__ __forceinline__ uint32_t f2tf(float x) {
    uint32_t r; asm("cvt.rna.tf32.f32 %0, %1;" : "=r"(r) : "f"(x)); return r;
}

__device__ __forceinline__ void mma_tf32(float* c, const uint32_t* a, const uint32_t* b) {
    asm volatile(
        "mma.sync.aligned.m16n8k8.row.col.f32.tf32.tf32.f32 "
        "{%0,%1,%2,%3}, {%4,%5,%6,%7}, {%8,%9}, {%0,%1,%2,%3};\n"
        : "+f"(c[0]), "+f"(c[1]), "+f"(c[2]), "+f"(c[3])
        : "r"(a[0]), "r"(a[1]), "r"(a[2]), "r"(a[3]), "r"(b[0]), "r"(b[1]));
}

__device__ __forceinline__ uint32_t smem_u32(const void* p) {
    uint32_t a;
    asm("{ .reg .u64 t; cvta.to.shared.u64 t, %1; cvt.u32.u64 %0, t; }" : "=r"(a) : "l"(p));
    return a;
}

__device__ __forceinline__ void cp16(uint32_t saddr, const void* g) {
    asm volatile("cp.async.cg.shared.global [%0], [%1], 16;" :: "r"(saddr), "l"(g));
}
#define CP_COMMIT() asm volatile("cp.async.commit_group;" ::: "memory")
#define CP_WAIT0()  asm volatile("cp.async.wait_group 0;" ::: "memory")

// ---------------- RoPE table ----------------
// theta_j = 1/(10000^(2j)/64); j>=5 -> inf -> theta=0 (fp32 overflow, matches ref)
__global__ void freq_rope_kernel(float* __restrict__ cosT, float* __restrict__ sinT) {
    int idx = blockIdx.x * blockDim.x + threadIdx.x;
    if (idx >= SS * (DK/2)) return;
    int s = idx / (DK/2);
    int j = idx % (DK/2);
    float p = powf(10000.0f, 2.0f * (float)j);
    float theta = 1.0f / (p / (float)DK);
    float ang = (float)s * theta;
    double a = (double)ang;
    cosT[idx] = (float)cos(a);
    sinT[idx] = (float)sin(a);
}

// Reference quirk: out1 = x1*c - x2*s ; out2 = x2*s + x1*c  (R4-identical)
__global__ void rope_kernel() {
    int idx = blockIdx.x * blockDim.x + threadIdx.x;
    const int nQ = BB*SS*HQ*(DK/2);
    const int nK = BB*SS*HKV*(DK/2);
    if (idx < nQ) {
        int pr = idx & 31;
        int t  = idx >> 5;
        int h  = t % HQ;  t /= HQ;
        int s  = t % SS;
        int b  = t / SS;
        float* p = g_Q + ((size_t)(b*SS + s))*DMODEL + h*DK + pr*2;
        float c  = g_cos[s*(DK/2) + pr];
        float sn = g_sin[s*(DK/2) + pr];
        float x1 = p[0], x2 = p[1];
        p[0] = x1*c - x2*sn;
        p[1] = x2*sn + x1*c;
    } else if (idx < nQ + nK) {
        int j  = idx - nQ;
        int pr = j & 31;
        int t  = j >> 5;
        int h  = t % HKV; t /= HKV;
        int s  = t % SS;
        int b  = t / SS;
        float* p = g_K + ((size_t)(b*SS + s))*KVD + h*DK + pr*2;
        float c  = g_cos[s*(DK/2) + pr];
        float sn = g_sin[s*(DK/2) + pr];
        float x1 = p[0], x2 = p[1];
        p[0] = x1*c - x2*sn;
        p[1] = x2*sn + x1*c;
    }
}

// ---------------- tf32 GEMM, interleaved-fragment smem, 2 CTA/SM -------------
// C[M,N] = A[M,Kd]*W[N,Kd]^T + bias.  Values/order identical to R2 kernel.
// A quads {A[r][k],A[r+8][k],A[r][k+4],A[r+8][k+4]} at idx*20 (idx=(rg*2+ks)*8+r1)
//   -> A-frag = 1 LDS.128.
// B pairs {B[c][k],B[c][k+4]} in (ks,q)-planes stride 264 -> B-frag = 1 LDS.64.
#define AQ_ST 20
#define AS_WORDS 2560   // 127*20+16 = 2556
#define BP_ST 264
#define BS_WORDS 2112   // 7*264 + 254 + 2 = 2104

__device__ __forceinline__ void gemm_body(
        const float* __restrict__ A, const float* __restrict__ W,
        const float* __restrict__ bias, float* __restrict__ C,
        int N, int Kd, int rowbase, int colbase) {
    __shared__ uint32_t As[2][AS_WORDS];
    __shared__ uint32_t Bs[2][BS_WORDS];
    int tid = threadIdx.x;
    int lane = tid & 31, warp = tid >> 5;
    int wm = warp >> 2, wn = warp & 3;
    int r1 = lane >> 2, q = lane & 3;

    float acc[4][4][4];
#pragma unroll
    for (int a = 0; a < 4; a++)
#pragma unroll
        for (int b = 0; b < 4; b++)
#pragma unroll
            for (int c = 0; c < 4; c++) acc[a][b][c] = 0.0f;

    // role split: warps 0-3 load/stage A, warps 4-7 load/stage B
    int isA = tid < 128;
    int t2  = tid & 127;
    int fr1 = t2 & 7;            // A: row-within-group
    int fj  = (t2 >> 3) & 1;     // A: k-chunk
    int frg = t2 >> 4;           // A: 16-row group
    int fidx = (frg*2 + fj)*8 + fr1;   // = t2-permuted, lane-contiguous
    int arow = rowbase + frg*16 + fr1;
    int bcol = colbase + t2;

    float4 ra[4];
    // prefetch k-tile 0
    if (isA) {
        const float* p0 = &A[(size_t)arow*Kd + fj*8];
        const float* p1 = &A[(size_t)(arow+8)*Kd + fj*8];
        ra[0] = *(const float4*)p0;  ra[1] = *(const float4*)(p0+4);
        ra[2] = *(const float4*)p1;  ra[3] = *(const float4*)(p1+4);
    } else {
        const float* p0 = &W[(size_t)bcol*Kd];
        ra[0] = *(const float4*)p0;      ra[1] = *(const float4*)(p0+4);
        ra[2] = *(const float4*)(p0+8);  ra[3] = *(const float4*)(p0+12);
    }
    // stage k-tile 0
    {
        const float* v = (const float*)ra;
        if (isA) {
            uint32_t* base = &As[0][fidx*AQ_ST];
#pragma unroll
            for (int qq = 0; qq < 4; qq++) {
                uint4 u = {f2tf(v[qq]), f2tf(v[8+qq]), f2tf(v[qq+4]), f2tf(v[8+qq+4])};
                *(uint4*)(base + qq*4) = u;
            }
        } else {
#pragma unroll
            for (int jj = 0; jj < 2; jj++)
#pragma unroll
                for (int qq = 0; qq < 4; qq++) {
                    uint2 u = {f2tf(v[jj*8+qq]), f2tf(v[jj*8+qq+4])};
                    *(uint2*)&Bs[0][(jj*4+qq)*BP_ST + t2*2] = u;
                }
        }
    }
    __syncthreads();

    int nk = Kd / 16;
    for (int t = 0; t < nk; t++) {
        int s = t & 1;
        if (t + 1 < nk) {
            int kb = (t+1)*16;
            if (isA) {
                const float* p0 = &A[(size_t)arow*Kd + kb + fj*8];
                const float* p1 = &A[(size_t)(arow+8)*Kd + kb + fj*8];
                ra[0] = *(const float4*)p0;  ra[1] = *(const float4*)(p0+4);
                ra[2] = *(const float4*)p1;  ra[3] = *(const float4*)(p1+4);
            } else {
                const float* p0 = &W[(size_t)bcol*Kd + kb];
                ra[0] = *(const float4*)p0;      ra[1] = *(const float4*)(p0+4);
                ra[2] = *(const float4*)(p0+8);  ra[3] = *(const float4*)(p0+12);
            }
        }
#pragma unroll
        for (int ks = 0; ks < 2; ks++) {
            uint32_t af[4][4], bf[4][2];
#pragma unroll
            for (int mi = 0; mi < 4; mi++) {
                int idx = ((wm*4 + mi)*2 + ks)*8 + r1;
                *(uint4*)af[mi] = *(const uint4*)&As[s][idx*AQ_ST + q*4];
            }
#pragma unroll
            for (int ni = 0; ni < 4; ni++) {
                int col = wn*32 + ni*8 + r1;
                *(uint2*)bf[ni] = *(const uint2*)&Bs[s][(ks*4+q)*BP_ST + col*2];
            }
#pragma unroll
            for (int mi = 0; mi < 4; mi++)
#pragma unroll
                for (int ni = 0; ni < 4; ni++)
                    mma_tf32(acc[mi][ni], af[mi], bf[ni]);
        }
        if (t + 1 < nk) {
            int sn = (t+1) & 1;
            const float* v = (const float*)ra;
            if (isA) {
                uint32_t* base = &As[sn][fidx*AQ_ST];
#pragma unroll
                for (int qq = 0; qq < 4; qq++) {
                    uint4 u = {f2tf(v[qq]), f2tf(v[8+qq]), f2tf(v[qq+4]), f2tf(v[8+qq+4])};
                    *(uint4*)(base + qq*4) = u;
                }
            } else {
#pragma unroll
                for (int jj = 0; jj < 2; jj++)
#pragma unroll
                    for (int qq = 0; qq < 4; qq++) {
                        uint2 u = {f2tf(v[jj*8+qq]), f2tf(v[jj*8+qq+4])};
                        *(uint2*)&Bs[sn][(jj*4+qq)*BP_ST + t2*2] = u;
                    }
            }
        }
        __syncthreads();
    }

#pragma unroll
    for (int mi = 0; mi < 4; mi++) {
        int row = rowbase + wm*64 + mi*16 + r1;
#pragma unroll
        for (int ni = 0; ni < 4; ni++) {
            int col = colbase + wn*32 + ni*8 + 2*q;
            float c0 = bias[col], c1 = bias[col+1];
            float2 v0 = {acc[mi][ni][0] + c0, acc[mi][ni][1] + c1};
            *(float2*)&C[(size_t)row*N + col] = v0;
            float2 v1 = {acc[mi][ni][2] + c0, acc[mi][ni][3] + c1};
            *(float2*)&C[(size_t)(row+8)*N + col] = v1;
        }
    }
}

// Fused Q+K+V projection (384 CTAs), RoPE applied by separate kernel after.
__global__ void __launch_bounds__(256, 2) gemm_qkv(
        const float* __restrict__ x,
        const float* __restrict__ wq, const float* __restrict__ bq,
        const float* __restrict__ wk, const float* __restrict__ bk,
        const float* __restrict__ wv, const float* __restrict__ bv) {
    int id = blockIdx.x;
    const float* W; const float* bias; float* C;
    int N, rowbase, colbase;
    if (id < 256) {
        W = wq; bias = bq; C = g_Q; N = DMODEL;
        rowbase = (id >> 3) * 128; colbase = (id & 7) * 128;
    } else if (id < 320) {
        int i = id - 256;
        W = wk; bias = bk; C = g_K; N = KVD;
        rowbase = (i >> 1) * 128; colbase = (i & 1) * 128;
    } else {
        int i = id - 320;
        W = wv; bias = bv; C = g_V; N = KVD;
        rowbase = (i >> 1) * 128; colbase = (i & 1) * 128;
    }
    gemm_body(x, W, bias, C, N, DMODEL, rowbase, colbase);
}

// Output projection.
__global__ void __launch_bounds__(256, 2) gemm_o(
        const float* __restrict__ A, const float* __restrict__ W,
        const float* __restrict__ bias, float* __restrict__ C) {
    gemm_body(A, W, bias, C, DMODEL, DMODEL, blockIdx.y*128, blockIdx.x*128);
}

// ---------------- flash attention (unchanged from R7, passing) ----------------
#define KP_ST 72
#define VP_ST 136
#define STAGE_W (64*KP_ST + 32*VP_ST)      // 8960 words
#define ATT_SMEM (2*STAGE_W*4 + 8192*4)    // 104448 bytes
#define P_ST 68

__device__ __forceinline__ void issue_tile(uint32_t rawK, uint32_t rawV,
                                           const float* Kb, const float* Vb,
                                           int k0, int tid) {
#pragma unroll
    for (int i = 0; i < 2; i++) {
        int task = tid + 256*i;
        int row = task >> 3, j = task & 7;
        const float* g = &Kb[(size_t)(k0 + row)*KVD + j*8];
        cp16(rawK + task*32,      g);
        cp16(rawK + task*32 + 16, g + 4);
    }
#pragma unroll
    for (int i = 0; i < 2; i++) {
        int task = tid + 256*i;
        int slot = task >> 4, seg = task & 15;
        int k = (slot >> 2)*8 + (slot & 3);
        cp16(rawV + task*32,      &Vb[(size_t)(k0 + k)*KVD + seg*4]);
        cp16(rawV + task*32 + 16, &Vb[(size_t)(k0 + k + 4)*KVD + seg*4]);
    }
    CP_COMMIT();
}

__device__ __forceinline__ void fill_stage(uint32_t* Kp, uint32_t* Vp,
                                           const float* RAW, int tid) {
#pragma unroll
    for (int i = 0; i < 2; i++) {
        int task = tid + 256*i;
        int row = task >> 3, j = task & 7;
        float4 a = *(const float4*)(RAW + task*8);
        float4 b = *(const float4*)(RAW + task*8 + 4);
        uint4 w0 = {f2tf(a.x), f2tf(b.x), f2tf(a.y), f2tf(b.y)};
        uint4 w1 = {f2tf(a.z), f2tf(b.z), f2tf(a.w), f2tf(b.w)};
        *(uint4*)&Kp[row*KP_ST + j*8]     = w0;
        *(uint4*)&Kp[row*KP_ST + j*8 + 4] = w1;
    }
    const float* RV = RAW + 4096;
#pragma unroll
    for (int i = 0; i < 2; i++) {
        int task = tid + 256*i;
        int slot = task >> 4, seg = task & 15;
        float4 a = *(const float4*)(RV + task*8);
        float4 b = *(const float4*)(RV + task*8 + 4);
        uint4 w0 = {f2tf(a.x), f2tf(b.x), f2tf(a.y), f2tf(b.y)};
        uint4 w1 = {f2tf(a.z), f2tf(b.z), f2tf(a.w), f2tf(b.w)};
        *(uint4*)&Vp[slot*VP_ST + seg*8]     = w0;
        *(uint4*)&Vp[slot*VP_ST + seg*8 + 4] = w1;
    }
}

__global__ void __launch_bounds__(256, 2) attn_tf32() {
    extern __shared__ uint32_t smA[];
    uint32_t* TF  = smA;
    float*    RAW = (float*)(smA + 2*STAGE_W);
    uint32_t rawK = smem_u32(RAW);
    uint32_t rawV = rawK + 4096*4;

    int tid = threadIdx.x, lane = tid & 31, warp = tid >> 5;
    int g = warp >> 2, sub = warp & 3;
    int qt = (int)gridDim.x - 1 - (int)blockIdx.x;
    int y = blockIdx.y;
    int b = y >> 3, kvh = (y >> 1) & 3, hg = y & 1;
    int h = kvh*4 + hg*2 + g;

    const float* Qb = g_Q + (size_t)b*SS*DMODEL + h*DK;
    const float* Kb = g_K + (size_t)b*SS*KVD + kvh*DK;
    const float* Vb = g_V + (size_t)b*SS*KVD + kvh*DK;
    int q0 = qt * 64;
    int r1 = lane >> 2;
    int q  = lane & 3;
    int qrow = 16*sub + r1;

    uint32_t qf[8][4];
#pragma unroll
    for (int kk = 0; kk < 8; kk++) {
        int d = kk*8 + q;
        const float* p = &Qb[(size_t)(q0 + qrow)*DMODEL + d];
        qf[kk][0] = f2tf(p[0] * 0.125f);
        qf[kk][1] = f2tf(p[(size_t)8*DMODEL] * 0.125f);
        qf[kk][2] = f2tf(p[4] * 0.125f);
        qf[kk][3] = f2tf(p[(size_t)8*DMODEL + 4] * 0.125f);
    }

    float m1 = -1e30f, m2 = -1e30f, l1 = 0.0f, l2 = 0.0f;
    float of[8][4];
#pragma unroll
    for (int n = 0; n < 8; n++)
#pragma unroll
        for (int j = 0; j < 4; j++) of[n][j] = 0.0f;

    issue_tile(rawK, rawV, Kb, Vb, 0, tid);
    CP_WAIT0();
    fill_stage(TF, TF + 64*KP_ST, RAW, tid);
    __syncthreads();

    for (int kt = 0; kt <= qt; kt++) {
        int s = kt & 1;
        const uint32_t* Kp = TF + s*STAGE_W;
        const uint32_t* Vp = Kp + 64*KP_ST;
        uint32_t* stageN = TF + (s^1)*STAGE_W;
        uint32_t* Pb = stageN + (g ? 64*KP_ST : 0);

        if (kt < qt) issue_tile(rawK, rawV, Kb, Vb, (kt+1)*64, tid);

        float sf[8][4];
#pragma unroll
        for (int n = 0; n < 8; n++)
#pragma unroll
            for (int j = 0; j < 4; j++) sf[n][j] = 0.0f;
#pragma unroll
        for (int n = 0; n < 8; n++) {
            int key = n*8 + r1;
#pragma unroll
            for (int kk = 0; kk < 8; kk++) {
                uint2 b2 = *(const uint2*)&Kp[key*KP_ST + kk*8 + 2*q];
                uint32_t bfr[2] = {b2.x, b2.y};
                mma_tf32(sf[n], qf[kk], bfr);
            }
        }

        if (kt == qt) {
#pragma unroll
            for (int n = 0; n < 8; n++) {
                int col = n*8 + 2*q;
                if (col     > qrow)     sf[n][0] = -1e30f;
                if (col + 1 > qrow)     sf[n][1] = -1e30f;
                if (col     > qrow + 8) sf[n][2] = -1e30f;
                if (col + 1 > qrow + 8) sf[n][3] = -1e30f;
            }
        }

        float mx1 = -1e30f, mx2 = -1e30f;
#pragma unroll
        for (int n = 0; n < 8; n++) {
            mx1 = fmaxf(mx1, fmaxf(sf[n][0], sf[n][1]));
            mx2 = fmaxf(mx2, fmaxf(sf[n][2], sf[n][3]));
        }
        mx1 = fmaxf(mx1, __shfl_xor_sync(0xffffffffu, mx1, 1));
        mx1 = fmaxf(mx1, __shfl_xor_sync(0xffffffffu, mx1, 2));
        mx2 = fmaxf(mx2, __shfl_xor_sync(0xffffffffu, mx2, 1));
        mx2 = fmaxf(mx2, __shfl_xor_sync(0xffffffffu, mx2, 2));
        float mn1 = fmaxf(m1, mx1), mn2 = fmaxf(m2, mx2);
        float c1 = __expf(m1 - mn1), c2 = __expf(m2 - mn2);
        float s1 = 0.0f, s2 = 0.0f;
#pragma unroll
        for (int n = 0; n < 8; n++) {
            sf[n][0] = __expf(sf[n][0] - mn1);
            sf[n][1] = __expf(sf[n][1] - mn1);
            sf[n][2] = __expf(sf[n][2] - mn2);
            sf[n][3] = __expf(sf[n][3] - mn2);
            s1 += sf[n][0] + sf[n][1];
            s2 += sf[n][2] + sf[n][3];
        }
        s1 += __shfl_xor_sync(0xffffffffu, s1, 1);
        s1 += __shfl_xor_sync(0xffffffffu, s1, 2);
        s2 += __shfl_xor_sync(0xffffffffu, s2, 1);
        s2 += __shfl_xor_sync(0xffffffffu, s2, 2);
        l1 = l1*c1 + s1;  l2 = l2*c2 + s2;
        m1 = mn1;         m2 = mn2;
#pragma unroll
        for (int n = 0; n < 8; n++) {
            of[n][0] *= c1; of[n][1] *= c1;
            of[n][2] *= c2; of[n][3] *= c2;
        }

#pragma unroll
        for (int n = 0; n < 8; n++) {
            uint2 w0 = {f2tf(sf[n][0]), f2tf(sf[n][1])};
            *(uint2*)&Pb[qrow*P_ST + n*8 + 2*q] = w0;
            uint2 w1 = {f2tf(sf[n][2]), f2tf(sf[n][3])};
            *(uint2*)&Pb[(qrow+8)*P_ST + n*8 + 2*q] = w1;
        }
        __syncwarp();

#pragma unroll
        for (int kk = 0; kk < 8; kk++) {
            uint32_t pa[4];
            pa[0] = Pb[qrow*P_ST + kk*8 + q];
            pa[1] = Pb[(qrow+8)*P_ST + kk*8 + q];
            pa[2] = Pb[qrow*P_ST + kk*8 + q + 4];
            pa[3] = Pb[(qrow+8)*P_ST + kk*8 + q + 4];
            int slot = kk*4 + q;
#pragma unroll
            for (int n = 0; n < 8; n++) {
                uint2 v2 = *(const uint2*)&Vp[slot*VP_ST + (n*8 + r1)*2];
                uint32_t vb[2] = {v2.x, v2.y};
                mma_tf32(of[n], pa, vb);
            }
        }

        __syncthreads();
        if (kt < qt) {
            CP_WAIT0();
            fill_stage(stageN, stageN + 64*KP_ST, RAW, tid);
        }
        __syncthreads();
    }

    float inv1 = 1.0f / l1, inv2 = 1.0f / l2;
    float* Ob = g_attn + (size_t)b*SS*DMODEL + h*DK;
#pragma unroll
    for (int n = 0; n < 8; n++) {
        int col = n*8 + 2*q;
        float2 v0 = {of[n][0]*inv1, of[n][1]*inv1};
        *(float2*)&Ob[(size_t)(q0 + qrow)*DMODEL + col] = v0;
        float2 v1 = {of[n][2]*inv2, of[n][3]*inv2};
        *(float2*)&Ob[(size_t)(q0 + qrow + 8)*DMODEL + col] = v1;
    }
}

// ---------------- launch ----------------
extern "C" void kernel_launch(void* const* d_in, const int* in_sizes, int n_in,
                              void* d_out, int out_size) {
    const float* x  = (const float*)d_in[0];
    const float* wq = (const float*)d_in[1];
    const float* bq = (const float*)d_in[2];
    const float* wk = (const float*)d_in[3];
    const float* bk = (const float*)d_in[4];
    const float* wv = (const float*)d_in[5];
    const float* bv = (const float*)d_in[6];
    const float* wo = (const float*)d_in[7];
    const float* bo = (const float*)d_in[8];
    float* out = (float*)d_out;

    float *A, *cT, *sT;
    cudaGetSymbolAddress((void**)&A,  g_attn);
    cudaGetSymbolAddress((void**)&cT, g_cos);
    cudaGetSymbolAddress((void**)&sT, g_sin);

    static int cfg_done = 0;
    if (!cfg_done) {
        cudaFuncSetAttribute(attn_tf32, cudaFuncAttributeMaxDynamicSharedMemorySize, ATT_SMEM);
        cfg_done = 1;
    }

    // RoPE tables
    freq_rope_kernel<<<(SS*(DK/2) + 255)/256, 256>>>(cT, sT);

    // fused Q+K+V projections
    gemm_qkv<<<384, 256>>>(x, wq, bq, wk, bk, wv, bv);

    // RoPE applied in-place on Q and K (standalone, bit-identical to R4)
    {
        int total = BB*SS*HQ*(DK/2) + BB*SS*HKV*(DK/2);
        rope_kernel<<<(total + 255)/256, 256>>>();
    }

    // attention (2 heads per CTA share K/V)
    attn_tf32<<<dim3(SS/64, BB*HKV*2), 256, ATT_SMEM>>>();

    // output projection
    gemm_o<<<dim3(DMODEL/128, BB*SS/128), 256>>>(A, wo, bo, out);
}

// round 9
// speedup vs baseline: 1.2668x; 1.2668x over previous
#include <cuda_runtime.h>
#include <math.h>
#include <stdint.h>

#define BB   2
#define SS   2048
#define DMODEL 1024
#define HQ   16
#define HKV  4
#define DK   64
#define KVD  256   // HKV*DK

// ---------------- scratch (no allocations allowed) ----------------
__device__ float g_Q[BB*SS*DMODEL];
__device__ float g_K[BB*SS*KVD];
__device__ float g_V[BB*SS*KVD];
__device__ float g_attn[BB*SS*DMODEL];
__device__ float g_cos[SS*(DK/2)];
__device__ float g_sin[SS*(DK/2)];

// ---------------- helpers ----------------
__device__ __forceinline__ uint32_t f2tf(float x) {
    uint32_t r; asm("cvt.rna.tf32.f32 %0, %1;" : "=r"(r) : "f"(x)); return r;
}

__device__ __forceinline__ void mma_tf32(float* c, const uint32_t* a, const uint32_t* b) {
    asm volatile(
        "mma.sync.aligned.m16n8k8.row.col.f32.tf32.tf32.f32 "
        "{%0,%1,%2,%3}, {%4,%5,%6,%7}, {%8,%9}, {%0,%1,%2,%3};\n"
        : "+f"(c[0]), "+f"(c[1]), "+f"(c[2]), "+f"(c[3])
        : "r"(a[0]), "r"(a[1]), "r"(a[2]), "r"(a[3]), "r"(b[0]), "r"(b[1]));
}

__device__ __forceinline__ uint32_t smem_u32(const void* p) {
    uint32_t a;
    asm("{ .reg .u64 t; cvta.to.shared.u64 t, %1; cvt.u32.u64 %0, t; }" : "=r"(a) : "l"(p));
    return a;
}

__device__ __forceinline__ void cp16(uint32_t saddr, const void* g) {
    asm volatile("cp.async.cg.shared.global [%0], [%1], 16;" :: "r"(saddr), "l"(g));
}
#define CP_COMMIT() asm volatile("cp.async.commit_group;" ::: "memory")
#define CP_WAIT0()  asm volatile("cp.async.wait_group 0;" ::: "memory")

// ---------------- RoPE table ----------------
// theta_j = 1/(10000^(2j)/64); j>=5 -> inf -> theta=0 (fp32 overflow, matches ref)
__global__ void freq_rope_kernel(float* __restrict__ cosT, float* __restrict__ sinT) {
    int idx = blockIdx.x * blockDim.x + threadIdx.x;
    if (idx >= SS * (DK/2)) return;
    int s = idx / (DK/2);
    int j = idx % (DK/2);
    float p = powf(10000.0f, 2.0f * (float)j);
    float theta = 1.0f / (p / (float)DK);
    float ang = (float)s * theta;
    double a = (double)ang;
    cosT[idx] = (float)cos(a);
    sinT[idx] = (float)sin(a);
}

// Reference quirk: out1 = x1*c - x2*s ; out2 = x2*s + x1*c  (R4-identical)
__global__ void rope_kernel() {
    int idx = blockIdx.x * blockDim.x + threadIdx.x;
    const int nQ = BB*SS*HQ*(DK/2);
    const int nK = BB*SS*HKV*(DK/2);
    if (idx < nQ) {
        int pr = idx & 31;
        int t  = idx >> 5;
        int h  = t % HQ;  t /= HQ;
        int s  = t % SS;
        int b  = t / SS;
        float* p = g_Q + ((size_t)(b*SS + s))*DMODEL + h*DK + pr*2;
        float c  = g_cos[s*(DK/2) + pr];
        float sn = g_sin[s*(DK/2) + pr];
        float x1 = p[0], x2 = p[1];
        p[0] = x1*c - x2*sn;
        p[1] = x2*sn + x1*c;
    } else if (idx < nQ + nK) {
        int j  = idx - nQ;
        int pr = j & 31;
        int t  = j >> 5;
        int h  = t % HKV; t /= HKV;
        int s  = t % SS;
        int b  = t / SS;
        float* p = g_K + ((size_t)(b*SS + s))*KVD + h*DK + pr*2;
        float c  = g_cos[s*(DK/2) + pr];
        float sn = g_sin[s*(DK/2) + pr];
        float x1 = p[0], x2 = p[1];
        p[0] = x1*c - x2*sn;
        p[1] = x2*sn + x1*c;
    }
}

// ---------------- tf32 GEMM body (R4-identical numerics and layout) ----------
#define GST 20

__device__ __forceinline__ void gemm_body(
        const float* __restrict__ A, const float* __restrict__ W,
        const float* __restrict__ bias, float* __restrict__ C,
        int N, int Kd, int rowbase, int colbase) {
    __shared__ uint32_t As[2][128*GST];
    __shared__ uint32_t Bs[2][128*GST];
    int tid = threadIdx.x;
    int lane = tid & 31, warp = tid >> 5;
    int wm = warp >> 2, wn = warp & 3;

    float acc[4][4][4];
#pragma unroll
    for (int a = 0; a < 4; a++)
#pragma unroll
        for (int b = 0; b < 4; b++)
#pragma unroll
            for (int c = 0; c < 4; c++) acc[a][b][c] = 0.0f;

    int lr = tid >> 2;
    int kc = (tid & 3) * 4;

    float4 pa[2], pw[2];
#pragma unroll
    for (int i = 0; i < 2; i++) {
        pa[i] = *(const float4*)&A[(size_t)(rowbase + lr + 64*i)*Kd + 0 + kc];
        pw[i] = *(const float4*)&W[(size_t)(colbase + lr + 64*i)*Kd + 0 + kc];
    }
#pragma unroll
    for (int i = 0; i < 2; i++) {
        uint4 ua = {f2tf(pa[i].x), f2tf(pa[i].y), f2tf(pa[i].z), f2tf(pa[i].w)};
        *(uint4*)&As[0][(lr + 64*i)*GST + kc] = ua;
        uint4 uw = {f2tf(pw[i].x), f2tf(pw[i].y), f2tf(pw[i].z), f2tf(pw[i].w)};
        *(uint4*)&Bs[0][(lr + 64*i)*GST + kc] = uw;
    }
    __syncthreads();

    int nk = Kd / 16;
    for (int t = 0; t < nk; t++) {
        int s = t & 1;
        if (t + 1 < nk) {
            int kb = (t+1)*16;
#pragma unroll
            for (int i = 0; i < 2; i++) {
                pa[i] = *(const float4*)&A[(size_t)(rowbase + lr + 64*i)*Kd + kb + kc];
                pw[i] = *(const float4*)&W[(size_t)(colbase + lr + 64*i)*Kd + kb + kc];
            }
        }
#pragma unroll
        for (int ks = 0; ks < 2; ks++) {
            int k0 = ks * 8;
            uint32_t af[4][4], bf[4][2];
#pragma unroll
            for (int mi = 0; mi < 4; mi++) {
                int row = wm*64 + mi*16 + (lane >> 2);
                const uint32_t* p = &As[s][row*GST + k0 + (lane & 3)];
                af[mi][0] = p[0];
                af[mi][1] = p[8*GST];
                af[mi][2] = p[4];
                af[mi][3] = p[8*GST + 4];
            }
#pragma unroll
            for (int ni = 0; ni < 4; ni++) {
                int col = wn*32 + ni*8 + (lane >> 2);
                const uint32_t* p = &Bs[s][col*GST + k0 + (lane & 3)];
                bf[ni][0] = p[0];
                bf[ni][1] = p[4];
            }
#pragma unroll
            for (int mi = 0; mi < 4; mi++)
#pragma unroll
                for (int ni = 0; ni < 4; ni++)
                    mma_tf32(acc[mi][ni], af[mi], bf[ni]);
        }
        if (t + 1 < nk) {
            int sn = (t+1) & 1;
#pragma unroll
            for (int i = 0; i < 2; i++) {
                uint4 ua = {f2tf(pa[i].x), f2tf(pa[i].y), f2tf(pa[i].z), f2tf(pa[i].w)};
                *(uint4*)&As[sn][(lr + 64*i)*GST + kc] = ua;
                uint4 uw = {f2tf(pw[i].x), f2tf(pw[i].y), f2tf(pw[i].z), f2tf(pw[i].w)};
                *(uint4*)&Bs[sn][(lr + 64*i)*GST + kc] = uw;
            }
        }
        __syncthreads();
    }

#pragma unroll
    for (int mi = 0; mi < 4; mi++) {
        int row = rowbase + wm*64 + mi*16 + (lane >> 2);
#pragma unroll
        for (int ni = 0; ni < 4; ni++) {
            int col = colbase + wn*32 + ni*8 + 2*(lane & 3);
            float c0 = bias[col], c1 = bias[col+1];
            float2 v0 = {acc[mi][ni][0] + c0, acc[mi][ni][1] + c1};
            *(float2*)&C[(size_t)row*N + col] = v0;
            float2 v1 = {acc[mi][ni][2] + c0, acc[mi][ni][3] + c1};
            *(float2*)&C[(size_t)(row+8)*N + col] = v1;
        }
    }
}

// Fused Q+K+V projection (384 CTAs), no rope here (standalone rope after).
__global__ void __launch_bounds__(256) gemm_qkv(
        const float* __restrict__ x,
        const float* __restrict__ wq, const float* __restrict__ bq,
        const float* __restrict__ wk, const float* __restrict__ bk,
        const float* __restrict__ wv, const float* __restrict__ bv) {
    int id = blockIdx.x;
    const float* W; const float* bias; float* C;
    int N, rowbase, colbase;
    if (id < 256) {
        W = wq; bias = bq; C = g_Q; N = DMODEL;
        rowbase = (id >> 3) * 128; colbase = (id & 7) * 128;
    } else if (id < 320) {
        int i = id - 256;
        W = wk; bias = bk; C = g_K; N = KVD;
        rowbase = (i >> 1) * 128; colbase = (i & 1) * 128;
    } else {
        int i = id - 320;
        W = wv; bias = bv; C = g_V; N = KVD;
        rowbase = (i >> 1) * 128; colbase = (i & 1) * 128;
    }
    gemm_body(x, W, bias, C, N, DMODEL, rowbase, colbase);
}

// Output projection.
__global__ void __launch_bounds__(256) gemm_o(
        const float* __restrict__ A, const float* __restrict__ W,
        const float* __restrict__ bias, float* __restrict__ C) {
    gemm_body(A, W, bias, C, DMODEL, DMODEL, blockIdx.y*128, blockIdx.x*128);
}

// ---------------- flash attention: R4 structure + pair-interleaved K/V --------
// CTA: 256 thr = 2 q-heads x 4 row-subtiles, 64 q-rows, shared K/V; 1 sync/iter;
// P transposed via in-quad shuffles (no smem round-trip).
// Kp [64 keys][72]: word key*72 + kk*8 + 2q = K[key][kk*8+q], +1 = K[key][kk*8+q+4]
//   -> S-loop B-frag = 1 LDS.64 (bank-verified CF).
// Vp [32 slots][136]: slot = kk*4+q, word slot*136 + d*2 = V[kk*8+q][d], +1 = V[kk*8+q+4][d]
//   -> PV B-frag = 1 LDS.64 (bank-verified CF).
// RAW written by cp.async in the exact per-task order fill_stage reads it
// (same-thread bytes; cp.async.wait_group visibility is per-thread).
#define KP_ST 72
#define VP_ST 136
#define STAGE_W (64*KP_ST + 32*VP_ST)      // 8960 words
#define ATT_SMEM (2*STAGE_W*4 + 8192*4)    // 104448 bytes

__device__ __forceinline__ void issue_tile(uint32_t rawK, uint32_t rawV,
                                           const float* Kb, const float* Vb,
                                           int k0, int tid) {
#pragma unroll
    for (int i = 0; i < 2; i++) {
        int task = tid + 256*i;
        int row = task >> 3, j = task & 7;
        const float* g = &Kb[(size_t)(k0 + row)*KVD + j*8];
        cp16(rawK + task*32,      g);
        cp16(rawK + task*32 + 16, g + 4);
    }
#pragma unroll
    for (int i = 0; i < 2; i++) {
        int task = tid + 256*i;
        int slot = task >> 4, seg = task & 15;
        int k = (slot >> 2)*8 + (slot & 3);
        cp16(rawV + task*32,      &Vb[(size_t)(k0 + k)*KVD + seg*4]);
        cp16(rawV + task*32 + 16, &Vb[(size_t)(k0 + k + 4)*KVD + seg*4]);
    }
    CP_COMMIT();
}

__device__ __forceinline__ void fill_stage(uint32_t* Kp, uint32_t* Vp,
                                           const float* RAW, int tid) {
#pragma unroll
    for (int i = 0; i < 2; i++) {
        int task = tid + 256*i;
        int row = task >> 3, j = task & 7;
        float4 a = *(const float4*)(RAW + task*8);
        float4 b = *(const float4*)(RAW + task*8 + 4);
        uint4 w0 = {f2tf(a.x), f2tf(b.x), f2tf(a.y), f2tf(b.y)};
        uint4 w1 = {f2tf(a.z), f2tf(b.z), f2tf(a.w), f2tf(b.w)};
        *(uint4*)&Kp[row*KP_ST + j*8]     = w0;
        *(uint4*)&Kp[row*KP_ST + j*8 + 4] = w1;
    }
    const float* RV = RAW + 4096;
#pragma unroll
    for (int i = 0; i < 2; i++) {
        int task = tid + 256*i;
        int slot = task >> 4, seg = task & 15;
        float4 a = *(const float4*)(RV + task*8);
        float4 b = *(const float4*)(RV + task*8 + 4);
        uint4 w0 = {f2tf(a.x), f2tf(b.x), f2tf(a.y), f2tf(b.y)};
        uint4 w1 = {f2tf(a.z), f2tf(b.z), f2tf(a.w), f2tf(b.w)};
        *(uint4*)&Vp[slot*VP_ST + seg*8]     = w0;
        *(uint4*)&Vp[slot*VP_ST + seg*8 + 4] = w1;
    }
}

__global__ void __launch_bounds__(256, 2) attn_tf32() {
    extern __shared__ uint32_t smA[];
    uint32_t* TF  = smA;                       // 2 tf32 stages
    float*    RAW = (float*)(smA + 2*STAGE_W); // K raw [0,4096), V raw [4096,8192)
    uint32_t rawK = smem_u32(RAW);
    uint32_t rawV = rawK + 4096*4;

    int tid = threadIdx.x, lane = tid & 31, warp = tid >> 5;
    int g = warp >> 2, sub = warp & 3;
    int qt = (int)gridDim.x - 1 - (int)blockIdx.x;
    int y = blockIdx.y;
    int b = y >> 3, kvh = (y >> 1) & 3, hg = y & 1;
    int h = kvh*4 + hg*2 + g;

    const float* Qb = g_Q + (size_t)b*SS*DMODEL + h*DK;
    const float* Kb = g_K + (size_t)b*SS*KVD + kvh*DK;
    const float* Vb = g_V + (size_t)b*SS*KVD + kvh*DK;
    int q0 = qt * 64;
    int r1 = lane >> 2;
    int q  = lane & 3;
    int qrow = 16*sub + r1;

    // Q fragments, pre-scaled by 1/sqrt(64)
    uint32_t qf[8][4];
#pragma unroll
    for (int kk = 0; kk < 8; kk++) {
        int d = kk*8 + q;
        const float* p = &Qb[(size_t)(q0 + qrow)*DMODEL + d];
        qf[kk][0] = f2tf(p[0] * 0.125f);
        qf[kk][1] = f2tf(p[(size_t)8*DMODEL] * 0.125f);
        qf[kk][2] = f2tf(p[4] * 0.125f);
        qf[kk][3] = f2tf(p[(size_t)8*DMODEL + 4] * 0.125f);
    }

    float m1 = -1e30f, m2 = -1e30f, l1 = 0.0f, l2 = 0.0f;
    float of[8][4];
#pragma unroll
    for (int n = 0; n < 8; n++)
#pragma unroll
        for (int j = 0; j < 4; j++) of[n][j] = 0.0f;

    // shuffle-transpose lane math (R4)
    int srcA = (lane & ~3) | (q >> 1);
    int srcB = srcA + 2;
    int qodd = q & 1;

    // prefetch tile 0 into RAW, convert into stage 0 (same-thread bytes)
    issue_tile(rawK, rawV, Kb, Vb, 0, tid);
    CP_WAIT0();
    fill_stage(TF, TF + 64*KP_ST, RAW, tid);
    __syncthreads();

    for (int kt = 0; kt <= qt; kt++) {
        int s = kt & 1;
        const uint32_t* Kp = TF + s*STAGE_W;
        const uint32_t* Vp = Kp + 64*KP_ST;
        uint32_t* stageN = TF + (s^1)*STAGE_W;

        // issue cp.async for next tile
        if (kt < qt) issue_tile(rawK, rawV, Kb, Vb, (kt+1)*64, tid);

        // S = (Q/8) K^T   (B-frag = 1 LDS.64)
        float sf[8][4];
#pragma unroll
        for (int n = 0; n < 8; n++)
#pragma unroll
            for (int j = 0; j < 4; j++) sf[n][j] = 0.0f;
#pragma unroll
        for (int n = 0; n < 8; n++) {
            int key = n*8 + r1;
#pragma unroll
            for (int kk = 0; kk < 8; kk++) {
                uint2 b2 = *(const uint2*)&Kp[key*KP_ST + kk*8 + 2*q];
                uint32_t bfr[2] = {b2.x, b2.y};
                mma_tf32(sf[n], qf[kk], bfr);
            }
        }

        // causal mask on diagonal tile
        if (kt == qt) {
#pragma unroll
            for (int n = 0; n < 8; n++) {
                int col = n*8 + 2*q;
                if (col     > qrow)     sf[n][0] = -1e30f;
                if (col + 1 > qrow)     sf[n][1] = -1e30f;
                if (col     > qrow + 8) sf[n][2] = -1e30f;
                if (col + 1 > qrow + 8) sf[n][3] = -1e30f;
            }
        }

        // online softmax
        float mx1 = -1e30f, mx2 = -1e30f;
#pragma unroll
        for (int n = 0; n < 8; n++) {
            mx1 = fmaxf(mx1, fmaxf(sf[n][0], sf[n][1]));
            mx2 = fmaxf(mx2, fmaxf(sf[n][2], sf[n][3]));
        }
        mx1 = fmaxf(mx1, __shfl_xor_sync(0xffffffffu, mx1, 1));
        mx1 = fmaxf(mx1, __shfl_xor_sync(0xffffffffu, mx1, 2));
        mx2 = fmaxf(mx2, __shfl_xor_sync(0xffffffffu, mx2, 1));
        mx2 = fmaxf(mx2, __shfl_xor_sync(0xffffffffu, mx2, 2));
        float mn1 = fmaxf(m1, mx1), mn2 = fmaxf(m2, mx2);
        float c1 = __expf(m1 - mn1), c2 = __expf(m2 - mn2);
        float s1 = 0.0f, s2 = 0.0f;
#pragma unroll
        for (int n = 0; n < 8; n++) {
            sf[n][0] = __expf(sf[n][0] - mn1);
            sf[n][1] = __expf(sf[n][1] - mn1);
            sf[n][2] = __expf(sf[n][2] - mn2);
            sf[n][3] = __expf(sf[n][3] - mn2);
            s1 += sf[n][0] + sf[n][1];
            s2 += sf[n][2] + sf[n][3];
        }
        s1 += __shfl_xor_sync(0xffffffffu, s1, 1);
        s1 += __shfl_xor_sync(0xffffffffu, s1, 2);
        s2 += __shfl_xor_sync(0xffffffffu, s2, 1);
        s2 += __shfl_xor_sync(0xffffffffu, s2, 2);
        l1 = l1*c1 + s1;  l2 = l2*c2 + s2;
        m1 = mn1;         m2 = mn2;
#pragma unroll
        for (int n = 0; n < 8; n++) {
            of[n][0] *= c1; of[n][1] *= c1;
            of[n][2] *= c2; of[n][3] *= c2;
        }

        // P -> tf32 (same cvt point)
        uint32_t pt[8][4];
#pragma unroll
        for (int n = 0; n < 8; n++) {
            pt[n][0] = f2tf(sf[n][0]);
            pt[n][1] = f2tf(sf[n][1]);
            pt[n][2] = f2tf(sf[n][2]);
            pt[n][3] = f2tf(sf[n][3]);
        }

        // O += P V ; A-frag of P via in-quad shuffles, V-frag = 1 LDS.64
#pragma unroll
        for (int kk = 0; kk < 8; kk++) {
            uint32_t v00 = __shfl_sync(0xffffffffu, pt[kk][0], srcA);
            uint32_t v01 = __shfl_sync(0xffffffffu, pt[kk][1], srcA);
            uint32_t v10 = __shfl_sync(0xffffffffu, pt[kk][2], srcA);
            uint32_t v11 = __shfl_sync(0xffffffffu, pt[kk][3], srcA);
            uint32_t v20 = __shfl_sync(0xffffffffu, pt[kk][0], srcB);
            uint32_t v21 = __shfl_sync(0xffffffffu, pt[kk][1], srcB);
            uint32_t v30 = __shfl_sync(0xffffffffu, pt[kk][2], srcB);
            uint32_t v31 = __shfl_sync(0xffffffffu, pt[kk][3], srcB);
            uint32_t pa[4];
            pa[0] = qodd ? v01 : v00;   // P[r1  ][kk*8+q]
            pa[1] = qodd ? v11 : v10;   // P[r1+8][kk*8+q]
            pa[2] = qodd ? v21 : v20;   // P[r1  ][kk*8+q+4]
            pa[3] = qodd ? v31 : v30;   // P[r1+8][kk*8+q+4]
            int slot = kk*4 + q;
#pragma unroll
            for (int n = 0; n < 8; n++) {
                uint2 v2 = *(const uint2*)&Vp[slot*VP_ST + (n*8 + r1)*2];
                uint32_t vb[2] = {v2.x, v2.y};
                mma_tf32(of[n], pa, vb);
            }
        }

        // land next tile: wait own copies, cvt into the other stage
        if (kt < qt) {
            CP_WAIT0();
            fill_stage(stageN, stageN + 64*KP_ST, RAW, tid);
        }
        __syncthreads();   // stage ready; RAW reusable
    }

    float inv1 = 1.0f / l1, inv2 = 1.0f / l2;
    float* Ob = g_attn + (size_t)b*SS*DMODEL + h*DK;
#pragma unroll
    for (int n = 0; n < 8; n++) {
        int col = n*8 + 2*q;
        float2 v0 = {of[n][0]*inv1, of[n][1]*inv1};
        *(float2*)&Ob[(size_t)(q0 + qrow)*DMODEL + col] = v0;
        float2 v1 = {of[n][2]*inv2, of[n][3]*inv2};
        *(float2*)&Ob[(size_t)(q0 + qrow + 8)*DMODEL + col] = v1;
    }
}

// ---------------- launch ----------------
extern "C" void kernel_launch(void* const* d_in, const int* in_sizes, int n_in,
                              void* d_out, int out_size) {
    const float* x  = (const float*)d_in[0];
    const float* wq = (const float*)d_in[1];
    const float* bq = (const float*)d_in[2];
    const float* wk = (const float*)d_in[3];
    const float* bk = (const float*)d_in[4];
    const float* wv = (const float*)d_in[5];
    const float* bv = (const float*)d_in[6];
    const float* wo = (const float*)d_in[7];
    const float* bo = (const float*)d_in[8];
    float* out = (float*)d_out;

    float *A, *cT, *sT;
    cudaGetSymbolAddress((void**)&A,  g_attn);
    cudaGetSymbolAddress((void**)&cT, g_cos);
    cudaGetSymbolAddress((void**)&sT, g_sin);

    static int cfg_done = 0;
    if (!cfg_done) {
        cudaFuncSetAttribute(attn_tf32, cudaFuncAttributeMaxDynamicSharedMemorySize, ATT_SMEM);
        cfg_done = 1;
    }

    // RoPE tables
    freq_rope_kernel<<<(SS*(DK/2) + 255)/256, 256>>>(cT, sT);

    // fused Q+K+V projections (one launch)
    gemm_qkv<<<384, 256>>>(x, wq, bq, wk, bk, wv, bv);

    // RoPE applied in-place on Q and K (standalone, bit-identical to R4)
    {
        int total = BB*SS*HQ*(DK/2) + BB*SS*HKV*(DK/2);
        rope_kernel<<<(total + 255)/256, 256>>>();
    }

    // attention (2 heads per CTA share K/V)
    attn_tf32<<<dim3(SS/64, BB*HKV*2), 256, ATT_SMEM>>>();

    // output projection
    gemm_o<<<dim3(DMODEL/128, BB*SS/128), 256>>>(A, wo, bo, out);
}

// round 10
// speedup vs baseline: 1.4435x; 1.1394x over previous
#include <cuda_runtime.h>
#include <math.h>
#include <stdint.h>

#define BB   2
#define SS   2048
#define DMODEL 1024
#define HQ   16
#define HKV  4
#define DK   64
#define KVD  256   // HKV*DK

// ---------------- scratch (no allocations allowed) ----------------
__device__ float g_Q[BB*SS*DMODEL];
__device__ float g_K[BB*SS*KVD];
__device__ float g_V[BB*SS*KVD];
__device__ float g_attn[BB*SS*DMODEL];
__device__ float g_cos[SS*(DK/2)];
__device__ float g_sin[SS*(DK/2)];
// tf32 pre-converted, tile-interleaved K/V: 256 tiles x 4096 words each
__device__ uint32_t g_Kt[256*4096];
__device__ uint32_t g_Vt[256*4096];

// ---------------- helpers ----------------
__device__ __forceinline__ uint32_t f2tf(float x) {
    uint32_t r; asm("cvt.rna.tf32.f32 %0, %1;" : "=r"(r) : "f"(x)); return r;
}

__device__ __forceinline__ void mma_tf32(float* c, const uint32_t* a, const uint32_t* b) {
    asm volatile(
        "mma.sync.aligned.m16n8k8.row.col.f32.tf32.tf32.f32 "
        "{%0,%1,%2,%3}, {%4,%5,%6,%7}, {%8,%9}, {%0,%1,%2,%3};\n"
        : "+f"(c[0]), "+f"(c[1]), "+f"(c[2]), "+f"(c[3])
        : "r"(a[0]), "r"(a[1]), "r"(a[2]), "r"(a[3]), "r"(b[0]), "r"(b[1]));
}

__device__ __forceinline__ uint32_t smem_u32(const void* p) {
    uint32_t a;
    asm("{ .reg .u64 t; cvta.to.shared.u64 t, %1; cvt.u32.u64 %0, t; }" : "=r"(a) : "l"(p));
    return a;
}

__device__ __forceinline__ void cp16(uint32_t saddr, const void* g) {
    asm volatile("cp.async.cg.shared.global [%0], [%1], 16;" :: "r"(saddr), "l"(g));
}
#define CP_COMMIT() asm volatile("cp.async.commit_group;" ::: "memory")
#define CP_WAIT0()  asm volatile("cp.async.wait_group 0;" ::: "memory")

// ---------------- RoPE table ----------------
// theta_j = 1/(10000^(2j)/64); j>=5 -> inf -> theta=0 (fp32 overflow, matches ref)
__global__ void freq_rope_kernel(float* __restrict__ cosT, float* __restrict__ sinT) {
    int idx = blockIdx.x * blockDim.x + threadIdx.x;
    if (idx >= SS * (DK/2)) return;
    int s = idx / (DK/2);
    int j = idx % (DK/2);
    float p = powf(10000.0f, 2.0f * (float)j);
    float theta = 1.0f / (p / (float)DK);
    float ang = (float)s * theta;
    double a = (double)ang;
    cosT[idx] = (float)cos(a);
    sinT[idx] = (float)sin(a);
}

// Reference quirk: out1 = x1*c - x2*s ; out2 = x2*s + x1*c  (R4-identical)
__global__ void rope_kernel() {
    int idx = blockIdx.x * blockDim.x + threadIdx.x;
    const int nQ = BB*SS*HQ*(DK/2);
    const int nK = BB*SS*HKV*(DK/2);
    if (idx < nQ) {
        int pr = idx & 31;
        int t  = idx >> 5;
        int h  = t % HQ;  t /= HQ;
        int s  = t % SS;
        int b  = t / SS;
        float* p = g_Q + ((size_t)(b*SS + s))*DMODEL + h*DK + pr*2;
        float c  = g_cos[s*(DK/2) + pr];
        float sn = g_sin[s*(DK/2) + pr];
        float x1 = p[0], x2 = p[1];
        p[0] = x1*c - x2*sn;
        p[1] = x2*sn + x1*c;
    } else if (idx < nQ + nK) {
        int j  = idx - nQ;
        int pr = j & 31;
        int t  = j >> 5;
        int h  = t % HKV; t /= HKV;
        int s  = t % SS;
        int b  = t / SS;
        float* p = g_K + ((size_t)(b*SS + s))*KVD + h*DK + pr*2;
        float c  = g_cos[s*(DK/2) + pr];
        float sn = g_sin[s*(DK/2) + pr];
        float x1 = p[0], x2 = p[1];
        p[0] = x1*c - x2*sn;
        p[1] = x2*sn + x1*c;
    }
}

// ---------------- prep: K/V -> tf32, tile-interleaved gmem -------------------
// K tile word layout (dense 64 words/row): w = kk*8 + 2q + h  <->  col = kk*8+q+4h
// V tile word layout (dense 128 words/slot): w = d*2 + h <-> V[(slot>>2)*8+(slot&3)+4h][d]
__global__ void prep_kv() {
    int idx = blockIdx.x * blockDim.x + threadIdx.x;
    const int NK = 256*4096;
    if (idx < NK) {
        int w = idx & 63, row = (idx >> 6) & 63, tile = (idx >> 12) & 31;
        int kvh = (idx >> 17) & 3, b = idx >> 19;
        int kk = w >> 3, t = w & 7, h = t & 1, q = t >> 1;
        int col = kk*8 + q + 4*h;
        float v = g_K[((size_t)(b*SS + tile*64 + row))*KVD + kvh*DK + col];
        g_Kt[idx] = f2tf(v);
    } else {
        int j = idx - NK;
        int w = j & 127, slot = (j >> 7) & 31, tile = (j >> 12) & 31;
        int kvh = (j >> 17) & 3, b = j >> 19;
        int h = w & 1, d = w >> 1;
        int k = (slot >> 2)*8 + (slot & 3) + 4*h;
        float v = g_V[((size_t)(b*SS + tile*64 + k))*KVD + kvh*DK + d];
        g_Vt[j] = f2tf(v);
    }
}

// ---------------- tf32 GEMM body (R4-identical numerics and layout) ----------
#define GST 20

__device__ __forceinline__ void gemm_body(
        const float* __restrict__ A, const float* __restrict__ W,
        const float* __restrict__ bias, float* __restrict__ C,
        int N, int Kd, int rowbase, int colbase) {
    __shared__ uint32_t As[2][128*GST];
    __shared__ uint32_t Bs[2][128*GST];
    int tid = threadIdx.x;
    int lane = tid & 31, warp = tid >> 5;
    int wm = warp >> 2, wn = warp & 3;

    float acc[4][4][4];
#pragma unroll
    for (int a = 0; a < 4; a++)
#pragma unroll
        for (int b = 0; b < 4; b++)
#pragma unroll
            for (int c = 0; c < 4; c++) acc[a][b][c] = 0.0f;

    int lr = tid >> 2;
    int kc = (tid & 3) * 4;

    float4 pa[2], pw[2];
#pragma unroll
    for (int i = 0; i < 2; i++) {
        pa[i] = *(const float4*)&A[(size_t)(rowbase + lr + 64*i)*Kd + 0 + kc];
        pw[i] = *(const float4*)&W[(size_t)(colbase + lr + 64*i)*Kd + 0 + kc];
    }
#pragma unroll
    for (int i = 0; i < 2; i++) {
        uint4 ua = {f2tf(pa[i].x), f2tf(pa[i].y), f2tf(pa[i].z), f2tf(pa[i].w)};
        *(uint4*)&As[0][(lr + 64*i)*GST + kc] = ua;
        uint4 uw = {f2tf(pw[i].x), f2tf(pw[i].y), f2tf(pw[i].z), f2tf(pw[i].w)};
        *(uint4*)&Bs[0][(lr + 64*i)*GST + kc] = uw;
    }
    __syncthreads();

    int nk = Kd / 16;
    for (int t = 0; t < nk; t++) {
        int s = t & 1;
        if (t + 1 < nk) {
            int kb = (t+1)*16;
#pragma unroll
            for (int i = 0; i < 2; i++) {
                pa[i] = *(const float4*)&A[(size_t)(rowbase + lr + 64*i)*Kd + kb + kc];
                pw[i] = *(const float4*)&W[(size_t)(colbase + lr + 64*i)*Kd + kb + kc];
            }
        }
#pragma unroll
        for (int ks = 0; ks < 2; ks++) {
            int k0 = ks * 8;
            uint32_t af[4][4], bf[4][2];
#pragma unroll
            for (int mi = 0; mi < 4; mi++) {
                int row = wm*64 + mi*16 + (lane >> 2);
                const uint32_t* p = &As[s][row*GST + k0 + (lane & 3)];
                af[mi][0] = p[0];
                af[mi][1] = p[8*GST];
                af[mi][2] = p[4];
                af[mi][3] = p[8*GST + 4];
            }
#pragma unroll
            for (int ni = 0; ni < 4; ni++) {
                int col = wn*32 + ni*8 + (lane >> 2);
                const uint32_t* p = &Bs[s][col*GST + k0 + (lane & 3)];
                bf[ni][0] = p[0];
                bf[ni][1] = p[4];
            }
#pragma unroll
            for (int mi = 0; mi < 4; mi++)
#pragma unroll
                for (int ni = 0; ni < 4; ni++)
                    mma_tf32(acc[mi][ni], af[mi], bf[ni]);
        }
        if (t + 1 < nk) {
            int sn = (t+1) & 1;
#pragma unroll
            for (int i = 0; i < 2; i++) {
                uint4 ua = {f2tf(pa[i].x), f2tf(pa[i].y), f2tf(pa[i].z), f2tf(pa[i].w)};
                *(uint4*)&As[sn][(lr + 64*i)*GST + kc] = ua;
                uint4 uw = {f2tf(pw[i].x), f2tf(pw[i].y), f2tf(pw[i].z), f2tf(pw[i].w)};
                *(uint4*)&Bs[sn][(lr + 64*i)*GST + kc] = uw;
            }
        }
        __syncthreads();
    }

#pragma unroll
    for (int mi = 0; mi < 4; mi++) {
        int row = rowbase + wm*64 + mi*16 + (lane >> 2);
#pragma unroll
        for (int ni = 0; ni < 4; ni++) {
            int col = colbase + wn*32 + ni*8 + 2*(lane & 3);
            float c0 = bias[col], c1 = bias[col+1];
            float2 v0 = {acc[mi][ni][0] + c0, acc[mi][ni][1] + c1};
            *(float2*)&C[(size_t)row*N + col] = v0;
            float2 v1 = {acc[mi][ni][2] + c0, acc[mi][ni][3] + c1};
            *(float2*)&C[(size_t)(row+8)*N + col] = v1;
        }
    }
}

// Fused Q+K+V projection (384 CTAs).
__global__ void __launch_bounds__(256) gemm_qkv(
        const float* __restrict__ x,
        const float* __restrict__ wq, const float* __restrict__ bq,
        const float* __restrict__ wk, const float* __restrict__ bk,
        const float* __restrict__ wv, const float* __restrict__ bv) {
    int id = blockIdx.x;
    const float* W; const float* bias; float* C;
    int N, rowbase, colbase;
    if (id < 256) {
        W = wq; bias = bq; C = g_Q; N = DMODEL;
        rowbase = (id >> 3) * 128; colbase = (id & 7) * 128;
    } else if (id < 320) {
        int i = id - 256;
        W = wk; bias = bk; C = g_K; N = KVD;
        rowbase = (i >> 1) * 128; colbase = (i & 1) * 128;
    } else {
        int i = id - 320;
        W = wv; bias = bv; C = g_V; N = KVD;
        rowbase = (i >> 1) * 128; colbase = (i & 1) * 128;
    }
    gemm_body(x, W, bias, C, N, DMODEL, rowbase, colbase);
}

// Output projection.
__global__ void __launch_bounds__(256) gemm_o(
        const float* __restrict__ A, const float* __restrict__ W,
        const float* __restrict__ bias, float* __restrict__ C) {
    gemm_body(A, W, bias, C, DMODEL, DMODEL, blockIdx.y*128, blockIdx.x*128);
}

// ---------------- flash attention: direct cp.async of pre-formatted tiles ----
// CTA: 256 thr = 2 q-heads x 4 row-subtiles, 64 q-rows, shared K/V; 1 sync/iter;
// P transposed via in-quad shuffles. No per-step cvt, no staging STS.
// Kp smem [64 rows][72]: words kk*8+2q(+1) = {K[key][kk*8+q], K[key][kk*8+q+4]}
// Vp smem [32 slots][136]: words d*2(+1) = {V[k][d], V[k+4][d]}, k=(slot>>2)*8+(slot&3)
// cp.async copies dense gmem tile rows into padded smem rows (CF by phase).
#define KP_ST 72
#define VP_ST 136
#define STAGE_W (64*KP_ST + 32*VP_ST)      // 8960 words
#define ATT_SMEM (2*STAGE_W*4)             // 71680 bytes

__device__ __forceinline__ void issue_tile(uint32_t dstK, uint32_t dstV,
                                           const uint32_t* Kt, const uint32_t* Vt,
                                           int kt, int tid) {
    const char* srcK = (const char*)(Kt + (size_t)kt*4096);
    const char* srcV = (const char*)(Vt + (size_t)kt*4096);
#pragma unroll
    for (int i = 0; i < 4; i++) {
        int c = tid + 256*i;
        cp16(dstK + (c >> 4)*(KP_ST*4) + (c & 15)*16, srcK + c*16);
        cp16(dstV + (c >> 5)*(VP_ST*4) + (c & 31)*16, srcV + c*16);
    }
    CP_COMMIT();
}

__global__ void __launch_bounds__(256, 2) attn_tf32() {
    extern __shared__ uint32_t smA[];
    uint32_t smb = smem_u32(smA);

    int tid = threadIdx.x, lane = tid & 31, warp = tid >> 5;
    int g = warp >> 2, sub = warp & 3;
    int qt = (int)gridDim.x - 1 - (int)blockIdx.x;
    int y = blockIdx.y;
    int b = y >> 3, kvh = (y >> 1) & 3, hg = y & 1;
    int h = kvh*4 + hg*2 + g;

    const float* Qb = g_Q + (size_t)b*SS*DMODEL + h*DK;
    const uint32_t* Ktb = g_Kt + (size_t)((b*4 + kvh)*32)*4096;
    const uint32_t* Vtb = g_Vt + (size_t)((b*4 + kvh)*32)*4096;
    int q0 = qt * 64;
    int r1 = lane >> 2;
    int q  = lane & 3;
    int qrow = 16*sub + r1;

    // Q fragments, pre-scaled by 1/sqrt(64)
    uint32_t qf[8][4];
#pragma unroll
    for (int kk = 0; kk < 8; kk++) {
        int d = kk*8 + q;
        const float* p = &Qb[(size_t)(q0 + qrow)*DMODEL + d];
        qf[kk][0] = f2tf(p[0] * 0.125f);
        qf[kk][1] = f2tf(p[(size_t)8*DMODEL] * 0.125f);
        qf[kk][2] = f2tf(p[4] * 0.125f);
        qf[kk][3] = f2tf(p[(size_t)8*DMODEL + 4] * 0.125f);
    }

    float m1 = -1e30f, m2 = -1e30f, l1 = 0.0f, l2 = 0.0f;
    float of[8][4];
#pragma unroll
    for (int n = 0; n < 8; n++)
#pragma unroll
        for (int j = 0; j < 4; j++) of[n][j] = 0.0f;

    // shuffle-transpose lane math
    int srcA = (lane & ~3) | (q >> 1);
    int srcB = srcA + 2;
    int qodd = q & 1;

    // prefetch tile 0 directly into stage 0
    issue_tile(smb, smb + 64*KP_ST*4, Ktb, Vtb, 0, tid);
    CP_WAIT0();
    __syncthreads();

    for (int kt = 0; kt <= qt; kt++) {
        int s = kt & 1;
        const uint32_t* Kp = smA + s*STAGE_W;
        const uint32_t* Vp = Kp + 64*KP_ST;

        // issue cp.async for next tile into the other stage
        if (kt < qt) {
            uint32_t dst = smb + (s^1)*STAGE_W*4;
            issue_tile(dst, dst + 64*KP_ST*4, Ktb, Vtb, kt+1, tid);
        }

        // S = (Q/8) K^T   (B-frag = 1 LDS.64, CF)
        float sf[8][4];
#pragma unroll
        for (int n = 0; n < 8; n++)
#pragma unroll
            for (int j = 0; j < 4; j++) sf[n][j] = 0.0f;
#pragma unroll
        for (int n = 0; n < 8; n++) {
            int key = n*8 + r1;
#pragma unroll
            for (int kk = 0; kk < 8; kk++) {
                uint2 b2 = *(const uint2*)&Kp[key*KP_ST + kk*8 + 2*q];
                uint32_t bfr[2] = {b2.x, b2.y};
                mma_tf32(sf[n], qf[kk], bfr);
            }
        }

        // causal mask on diagonal tile
        if (kt == qt) {
#pragma unroll
            for (int n = 0; n < 8; n++) {
                int col = n*8 + 2*q;
                if (col     > qrow)     sf[n][0] = -1e30f;
                if (col + 1 > qrow)     sf[n][1] = -1e30f;
                if (col     > qrow + 8) sf[n][2] = -1e30f;
                if (col + 1 > qrow + 8) sf[n][3] = -1e30f;
            }
        }

        // online softmax
        float mx1 = -1e30f, mx2 = -1e30f;
#pragma unroll
        for (int n = 0; n < 8; n++) {
            mx1 = fmaxf(mx1, fmaxf(sf[n][0], sf[n][1]));
            mx2 = fmaxf(mx2, fmaxf(sf[n][2], sf[n][3]));
        }
        mx1 = fmaxf(mx1, __shfl_xor_sync(0xffffffffu, mx1, 1));
        mx1 = fmaxf(mx1, __shfl_xor_sync(0xffffffffu, mx1, 2));
        mx2 = fmaxf(mx2, __shfl_xor_sync(0xffffffffu, mx2, 1));
        mx2 = fmaxf(mx2, __shfl_xor_sync(0xffffffffu, mx2, 2));
        float mn1 = fmaxf(m1, mx1), mn2 = fmaxf(m2, mx2);
        float c1 = __expf(m1 - mn1), c2 = __expf(m2 - mn2);
        float s1 = 0.0f, s2 = 0.0f;
#pragma unroll
        for (int n = 0; n < 8; n++) {
            sf[n][0] = __expf(sf[n][0] - mn1);
            sf[n][1] = __expf(sf[n][1] - mn1);
            sf[n][2] = __expf(sf[n][2] - mn2);
            sf[n][3] = __expf(sf[n][3] - mn2);
            s1 += sf[n][0] + sf[n][1];
            s2 += sf[n][2] + sf[n][3];
        }
        s1 += __shfl_xor_sync(0xffffffffu, s1, 1);
        s1 += __shfl_xor_sync(0xffffffffu, s1, 2);
        s2 += __shfl_xor_sync(0xffffffffu, s2, 1);
        s2 += __shfl_xor_sync(0xffffffffu, s2, 2);
        l1 = l1*c1 + s1;  l2 = l2*c2 + s2;
        m1 = mn1;         m2 = mn2;
#pragma unroll
        for (int n = 0; n < 8; n++) {
            of[n][0] *= c1; of[n][1] *= c1;
            of[n][2] *= c2; of[n][3] *= c2;
        }

        // P -> tf32 (same cvt point)
        uint32_t pt[8][4];
#pragma unroll
        for (int n = 0; n < 8; n++) {
            pt[n][0] = f2tf(sf[n][0]);
            pt[n][1] = f2tf(sf[n][1]);
            pt[n][2] = f2tf(sf[n][2]);
            pt[n][3] = f2tf(sf[n][3]);
        }

        // O += P V ; A-frag of P via in-quad shuffles, V-frag = 1 LDS.64 (CF)
#pragma unroll
        for (int kk = 0; kk < 8; kk++) {
            uint32_t v00 = __shfl_sync(0xffffffffu, pt[kk][0], srcA);
            uint32_t v01 = __shfl_sync(0xffffffffu, pt[kk][1], srcA);
            uint32_t v10 = __shfl_sync(0xffffffffu, pt[kk][2], srcA);
            uint32_t v11 = __shfl_sync(0xffffffffu, pt[kk][3], srcA);
            uint32_t v20 = __shfl_sync(0xffffffffu, pt[kk][0], srcB);
            uint32_t v21 = __shfl_sync(0xffffffffu, pt[kk][1], srcB);
            uint32_t v30 = __shfl_sync(0xffffffffu, pt[kk][2], srcB);
            uint32_t v31 = __shfl_sync(0xffffffffu, pt[kk][3], srcB);
            uint32_t pa[4];
            pa[0] = qodd ? v01 : v00;   // P[r1  ][kk*8+q]
            pa[1] = qodd ? v11 : v10;   // P[r1+8][kk*8+q]
            pa[2] = qodd ? v21 : v20;   // P[r1  ][kk*8+q+4]
            pa[3] = qodd ? v31 : v30;   // P[r1+8][kk*8+q+4]
            int slot = kk*4 + q;
#pragma unroll
            for (int n = 0; n < 8; n++) {
                uint2 v2 = *(const uint2*)&Vp[slot*VP_ST + (n*8 + r1)*2];
                uint32_t vb[2] = {v2.x, v2.y};
                mma_tf32(of[n], pa, vb);
            }
        }

        // next stage: own copies done + barrier makes all threads' copies visible
        if (kt < qt) CP_WAIT0();
        __syncthreads();
    }

    float inv1 = 1.0f / l1, inv2 = 1.0f / l2;
    float* Ob = g_attn + (size_t)b*SS*DMODEL + h*DK;
#pragma unroll
    for (int n = 0; n < 8; n++) {
        int col = n*8 + 2*q;
        float2 v0 = {of[n][0]*inv1, of[n][1]*inv1};
        *(float2*)&Ob[(size_t)(q0 + qrow)*DMODEL + col] = v0;
        float2 v1 = {of[n][2]*inv2, of[n][3]*inv2};
        *(float2*)&Ob[(size_t)(q0 + qrow + 8)*DMODEL + col] = v1;
    }
}

// ---------------- launch ----------------
extern "C" void kernel_launch(void* const* d_in, const int* in_sizes, int n_in,
                              void* d_out, int out_size) {
    const float* x  = (const float*)d_in[0];
    const float* wq = (const float*)d_in[1];
    const float* bq = (const float*)d_in[2];
    const float* wk = (const float*)d_in[3];
    const float* bk = (const float*)d_in[4];
    const float* wv = (const float*)d_in[5];
    const float* bv = (const float*)d_in[6];
    const float* wo = (const float*)d_in[7];
    const float* bo = (const float*)d_in[8];
    float* out = (float*)d_out;

    float *A, *cT, *sT;
    cudaGetSymbolAddress((void**)&A,  g_attn);
    cudaGetSymbolAddress((void**)&cT, g_cos);
    cudaGetSymbolAddress((void**)&sT, g_sin);

    static int cfg_done = 0;
    if (!cfg_done) {
        cudaFuncSetAttribute(attn_tf32, cudaFuncAttributeMaxDynamicSharedMemorySize, ATT_SMEM);
        cfg_done = 1;
    }

    // RoPE tables
    freq_rope_kernel<<<(SS*(DK/2) + 255)/256, 256>>>(cT, sT);

    // fused Q+K+V projections (one launch)
    gemm_qkv<<<384, 256>>>(x, wq, bq, wk, bk, wv, bv);

    // RoPE applied in-place on Q and K
    {
        int total = BB*SS*HQ*(DK/2) + BB*SS*HKV*(DK/2);
        rope_kernel<<<(total + 255)/256, 256>>>();
    }

    // pre-convert K/V to tf32 tile-interleaved layouts
    prep_kv<<<(2*256*4096)/256, 256>>>();

    // attention (2 heads per CTA share K/V)
    attn_tf32<<<dim3(SS/64, BB*HKV*2), 256, ATT_SMEM>>>();

    // output projection
    gemm_o<<<dim3(DMODEL/128, BB*SS/128), 256>>>(A, wo, bo, out);
}

// round 11
// speedup vs baseline: 1.4501x; 1.0046x over previous
#include <cuda_runtime.h>
#include <math.h>
#include <stdint.h>

#define BB   2
#define SS   2048
#define DMODEL 1024
#define HQ   16
#define HKV  4
#define DK   64
#define KVD  256   // HKV*DK

// ---------------- scratch (no allocations allowed) ----------------
__device__ float g_Q[BB*SS*DMODEL];
__device__ float g_K[BB*SS*KVD];
__device__ float g_V[BB*SS*KVD];
__device__ float g_attn[BB*SS*DMODEL];
__device__ float g_cos[SS*(DK/2)];
__device__ float g_sin[SS*(DK/2)];
// tf32 pre-converted, tile-interleaved K/V: 256 tiles x 4096 words each
__device__ uint32_t g_Kt[256*4096];
__device__ uint32_t g_Vt[256*4096];

// ---------------- helpers ----------------
__device__ __forceinline__ uint32_t f2tf(float x) {
    uint32_t r; asm("cvt.rna.tf32.f32 %0, %1;" : "=r"(r) : "f"(x)); return r;
}

__device__ __forceinline__ void mma_tf32(float* c, const uint32_t* a, const uint32_t* b) {
    asm volatile(
        "mma.sync.aligned.m16n8k8.row.col.f32.tf32.tf32.f32 "
        "{%0,%1,%2,%3}, {%4,%5,%6,%7}, {%8,%9}, {%0,%1,%2,%3};\n"
        : "+f"(c[0]), "+f"(c[1]), "+f"(c[2]), "+f"(c[3])
        : "r"(a[0]), "r"(a[1]), "r"(a[2]), "r"(a[3]), "r"(b[0]), "r"(b[1]));
}

__device__ __forceinline__ uint32_t smem_u32(const void* p) {
    uint32_t a;
    asm("{ .reg .u64 t; cvta.to.shared.u64 t, %1; cvt.u32.u64 %0, t; }" : "=r"(a) : "l"(p));
    return a;
}

__device__ __forceinline__ void cp16(uint32_t saddr, const void* g) {
    asm volatile("cp.async.cg.shared.global [%0], [%1], 16;" :: "r"(saddr), "l"(g));
}
#define CP_COMMIT() asm volatile("cp.async.commit_group;" ::: "memory")
#define CP_WAIT0()  asm volatile("cp.async.wait_group 0;" ::: "memory")

// ---------------- RoPE table ----------------
// theta_j = 1/(10000^(2j)/64); j>=5 -> inf -> theta=0 (fp32 overflow, matches ref)
__global__ void freq_rope_kernel(float* __restrict__ cosT, float* __restrict__ sinT) {
    int idx = blockIdx.x * blockDim.x + threadIdx.x;
    if (idx >= SS * (DK/2)) return;
    int s = idx / (DK/2);
    int j = idx % (DK/2);
    float p = powf(10000.0f, 2.0f * (float)j);
    float theta = 1.0f / (p / (float)DK);
    float ang = (float)s * theta;
    double a = (double)ang;
    cosT[idx] = (float)cos(a);
    sinT[idx] = (float)sin(a);
}

// Reference quirk: out1 = x1*c - x2*s ; out2 = x2*s + x1*c  (R4-identical)
__global__ void rope_kernel() {
    int idx = blockIdx.x * blockDim.x + threadIdx.x;
    const int nQ = BB*SS*HQ*(DK/2);
    const int nK = BB*SS*HKV*(DK/2);
    if (idx < nQ) {
        int pr = idx & 31;
        int t  = idx >> 5;
        int h  = t % HQ;  t /= HQ;
        int s  = t % SS;
        int b  = t / SS;
        float* p = g_Q + ((size_t)(b*SS + s))*DMODEL + h*DK + pr*2;
        float c  = g_cos[s*(DK/2) + pr];
        float sn = g_sin[s*(DK/2) + pr];
        float x1 = p[0], x2 = p[1];
        p[0] = x1*c - x2*sn;
        p[1] = x2*sn + x1*c;
    } else if (idx < nQ + nK) {
        int j  = idx - nQ;
        int pr = j & 31;
        int t  = j >> 5;
        int h  = t % HKV; t /= HKV;
        int s  = t % SS;
        int b  = t / SS;
        float* p = g_K + ((size_t)(b*SS + s))*KVD + h*DK + pr*2;
        float c  = g_cos[s*(DK/2) + pr];
        float sn = g_sin[s*(DK/2) + pr];
        float x1 = p[0], x2 = p[1];
        p[0] = x1*c - x2*sn;
        p[1] = x2*sn + x1*c;
    }
}

// ---------------- prep: K/V -> tf32, tile-interleaved gmem -------------------
// K tile word layout (dense 64 words/row): w = kk*8 + 2q + h  <->  col = kk*8+q+4h
// V tile word layout (dense 128 words/slot): w = d*2 + h <-> V[(slot>>2)*8+(slot&3)+4h][d]
__global__ void prep_kv() {
    int idx = blockIdx.x * blockDim.x + threadIdx.x;
    const int NK = 256*4096;
    if (idx < NK) {
        int w = idx & 63, row = (idx >> 6) & 63, tile = (idx >> 12) & 31;
        int kvh = (idx >> 17) & 3, b = idx >> 19;
        int kk = w >> 3, t = w & 7, h = t & 1, q = t >> 1;
        int col = kk*8 + q + 4*h;
        float v = g_K[((size_t)(b*SS + tile*64 + row))*KVD + kvh*DK + col];
        g_Kt[idx] = f2tf(v);
    } else {
        int j = idx - NK;
        int w = j & 127, slot = (j >> 7) & 31, tile = (j >> 12) & 31;
        int kvh = (j >> 17) & 3, b = j >> 19;
        int h = w & 1, d = w >> 1;
        int k = (slot >> 2)*8 + (slot & 3) + 4*h;
        float v = g_V[((size_t)(b*SS + tile*64 + k))*KVD + kvh*DK + d];
        g_Vt[j] = f2tf(v);
    }
}

// ---------------- tf32 GEMM body (R4-identical numerics and layout) ----------
#define GST 20

__device__ __forceinline__ void gemm_body(
        const float* __restrict__ A, const float* __restrict__ W,
        const float* __restrict__ bias, float* __restrict__ C,
        int N, int Kd, int rowbase, int colbase) {
    __shared__ uint32_t As[2][128*GST];
    __shared__ uint32_t Bs[2][128*GST];
    int tid = threadIdx.x;
    int lane = tid & 31, warp = tid >> 5;
    int wm = warp >> 2, wn = warp & 3;

    float acc[4][4][4];
#pragma unroll
    for (int a = 0; a < 4; a++)
#pragma unroll
        for (int b = 0; b < 4; b++)
#pragma unroll
            for (int c = 0; c < 4; c++) acc[a][b][c] = 0.0f;

    int lr = tid >> 2;
    int kc = (tid & 3) * 4;

    float4 pa[2], pw[2];
#pragma unroll
    for (int i = 0; i < 2; i++) {
        pa[i] = *(const float4*)&A[(size_t)(rowbase + lr + 64*i)*Kd + 0 + kc];
        pw[i] = *(const float4*)&W[(size_t)(colbase + lr + 64*i)*Kd + 0 + kc];
    }
#pragma unroll
    for (int i = 0; i < 2; i++) {
        uint4 ua = {f2tf(pa[i].x), f2tf(pa[i].y), f2tf(pa[i].z), f2tf(pa[i].w)};
        *(uint4*)&As[0][(lr + 64*i)*GST + kc] = ua;
        uint4 uw = {f2tf(pw[i].x), f2tf(pw[i].y), f2tf(pw[i].z), f2tf(pw[i].w)};
        *(uint4*)&Bs[0][(lr + 64*i)*GST + kc] = uw;
    }
    __syncthreads();

    int nk = Kd / 16;
    for (int t = 0; t < nk; t++) {
        int s = t & 1;
        if (t + 1 < nk) {
            int kb = (t+1)*16;
#pragma unroll
            for (int i = 0; i < 2; i++) {
                pa[i] = *(const float4*)&A[(size_t)(rowbase + lr + 64*i)*Kd + kb + kc];
                pw[i] = *(const float4*)&W[(size_t)(colbase + lr + 64*i)*Kd + kb + kc];
            }
        }
#pragma unroll
        for (int ks = 0; ks < 2; ks++) {
            int k0 = ks * 8;
            uint32_t af[4][4], bf[4][2];
#pragma unroll
            for (int mi = 0; mi < 4; mi++) {
                int row = wm*64 + mi*16 + (lane >> 2);
                const uint32_t* p = &As[s][row*GST + k0 + (lane & 3)];
                af[mi][0] = p[0];
                af[mi][1] = p[8*GST];
                af[mi][2] = p[4];
                af[mi][3] = p[8*GST + 4];
            }
#pragma unroll
            for (int ni = 0; ni < 4; ni++) {
                int col = wn*32 + ni*8 + (lane >> 2);
                const uint32_t* p = &Bs[s][col*GST + k0 + (lane & 3)];
                bf[ni][0] = p[0];
                bf[ni][1] = p[4];
            }
#pragma unroll
            for (int mi = 0; mi < 4; mi++)
#pragma unroll
                for (int ni = 0; ni < 4; ni++)
                    mma_tf32(acc[mi][ni], af[mi], bf[ni]);
        }
        if (t + 1 < nk) {
            int sn = (t+1) & 1;
#pragma unroll
            for (int i = 0; i < 2; i++) {
                uint4 ua = {f2tf(pa[i].x), f2tf(pa[i].y), f2tf(pa[i].z), f2tf(pa[i].w)};
                *(uint4*)&As[sn][(lr + 64*i)*GST + kc] = ua;
                uint4 uw = {f2tf(pw[i].x), f2tf(pw[i].y), f2tf(pw[i].z), f2tf(pw[i].w)};
                *(uint4*)&Bs[sn][(lr + 64*i)*GST + kc] = uw;
            }
        }
        __syncthreads();
    }

#pragma unroll
    for (int mi = 0; mi < 4; mi++) {
        int row = rowbase + wm*64 + mi*16 + (lane >> 2);
#pragma unroll
        for (int ni = 0; ni < 4; ni++) {
            int col = colbase + wn*32 + ni*8 + 2*(lane & 3);
            float c0 = bias[col], c1 = bias[col+1];
            float2 v0 = {acc[mi][ni][0] + c0, acc[mi][ni][1] + c1};
            *(float2*)&C[(size_t)row*N + col] = v0;
            float2 v1 = {acc[mi][ni][2] + c0, acc[mi][ni][3] + c1};
            *(float2*)&C[(size_t)(row+8)*N + col] = v1;
        }
    }
}

// Fused Q+K+V projection (384 CTAs).
__global__ void __launch_bounds__(256) gemm_qkv(
        const float* __restrict__ x,
        const float* __restrict__ wq, const float* __restrict__ bq,
        const float* __restrict__ wk, const float* __restrict__ bk,
        const float* __restrict__ wv, const float* __restrict__ bv) {
    int id = blockIdx.x;
    const float* W; const float* bias; float* C;
    int N, rowbase, colbase;
    if (id < 256) {
        W = wq; bias = bq; C = g_Q; N = DMODEL;
        rowbase = (id >> 3) * 128; colbase = (id & 7) * 128;
    } else if (id < 320) {
        int i = id - 256;
        W = wk; bias = bk; C = g_K; N = KVD;
        rowbase = (i >> 1) * 128; colbase = (i & 1) * 128;
    } else {
        int i = id - 320;
        W = wv; bias = bv; C = g_V; N = KVD;
        rowbase = (i >> 1) * 128; colbase = (i & 1) * 128;
    }
    gemm_body(x, W, bias, C, N, DMODEL, rowbase, colbase);
}

// Output projection.
__global__ void __launch_bounds__(256) gemm_o(
        const float* __restrict__ A, const float* __restrict__ W,
        const float* __restrict__ bias, float* __restrict__ C) {
    gemm_body(A, W, bias, C, DMODEL, DMODEL, blockIdx.y*128, blockIdx.x*128);
}

// ---------------- flash attention: direct cp.async of pre-formatted tiles ----
// CTA: 256 thr = 2 q-heads x 4 row-subtiles, 64 q-rows, shared K/V; 1 sync/iter;
// P transposed via in-quad shuffles. No per-step cvt, no staging STS.
// S-loop nested kk-outer/n-inner: 8 independent accumulator chains (same
// per-accumulator kk order as before -> bit-identical values).
#define KP_ST 72
#define VP_ST 136
#define STAGE_W (64*KP_ST + 32*VP_ST)      // 8960 words
#define ATT_SMEM (2*STAGE_W*4)             // 71680 bytes

__device__ __forceinline__ void issue_tile(uint32_t dstK, uint32_t dstV,
                                           const uint32_t* Kt, const uint32_t* Vt,
                                           int kt, int tid) {
    const char* srcK = (const char*)(Kt + (size_t)kt*4096);
    const char* srcV = (const char*)(Vt + (size_t)kt*4096);
#pragma unroll
    for (int i = 0; i < 4; i++) {
        int c = tid + 256*i;
        cp16(dstK + (c >> 4)*(KP_ST*4) + (c & 15)*16, srcK + c*16);
        cp16(dstV + (c >> 5)*(VP_ST*4) + (c & 31)*16, srcV + c*16);
    }
    CP_COMMIT();
}

__global__ void __launch_bounds__(256, 2) attn_tf32() {
    extern __shared__ uint32_t smA[];
    uint32_t smb = smem_u32(smA);

    int tid = threadIdx.x, lane = tid & 31, warp = tid >> 5;
    int g = warp >> 2, sub = warp & 3;
    int qt = (int)gridDim.x - 1 - (int)blockIdx.x;
    int y = blockIdx.y;
    int b = y >> 3, kvh = (y >> 1) & 3, hg = y & 1;
    int h = kvh*4 + hg*2 + g;

    const float* Qb = g_Q + (size_t)b*SS*DMODEL + h*DK;
    const uint32_t* Ktb = g_Kt + (size_t)((b*4 + kvh)*32)*4096;
    const uint32_t* Vtb = g_Vt + (size_t)((b*4 + kvh)*32)*4096;
    int q0 = qt * 64;
    int r1 = lane >> 2;
    int q  = lane & 3;
    int qrow = 16*sub + r1;

    // Q fragments, pre-scaled by 1/sqrt(64)
    uint32_t qf[8][4];
#pragma unroll
    for (int kk = 0; kk < 8; kk++) {
        int d = kk*8 + q;
        const float* p = &Qb[(size_t)(q0 + qrow)*DMODEL + d];
        qf[kk][0] = f2tf(p[0] * 0.125f);
        qf[kk][1] = f2tf(p[(size_t)8*DMODEL] * 0.125f);
        qf[kk][2] = f2tf(p[4] * 0.125f);
        qf[kk][3] = f2tf(p[(size_t)8*DMODEL + 4] * 0.125f);
    }

    float m1 = -1e30f, m2 = -1e30f, l1 = 0.0f, l2 = 0.0f;
    float of[8][4];
#pragma unroll
    for (int n = 0; n < 8; n++)
#pragma unroll
        for (int j = 0; j < 4; j++) of[n][j] = 0.0f;

    // shuffle-transpose lane math
    int srcA = (lane & ~3) | (q >> 1);
    int srcB = srcA + 2;
    int qodd = q & 1;

    // prefetch tile 0 directly into stage 0
    issue_tile(smb, smb + 64*KP_ST*4, Ktb, Vtb, 0, tid);
    CP_WAIT0();
    __syncthreads();

    for (int kt = 0; kt <= qt; kt++) {
        int s = kt & 1;
        const uint32_t* Kp = smA + s*STAGE_W;
        const uint32_t* Vp = Kp + 64*KP_ST;

        // issue cp.async for next tile into the other stage
        if (kt < qt) {
            uint32_t dst = smb + (s^1)*STAGE_W*4;
            issue_tile(dst, dst + 64*KP_ST*4, Ktb, Vtb, kt+1, tid);
        }

        // S = (Q/8) K^T   (kk-outer: 8 independent accumulator chains)
        float sf[8][4];
#pragma unroll
        for (int n = 0; n < 8; n++)
#pragma unroll
            for (int j = 0; j < 4; j++) sf[n][j] = 0.0f;
#pragma unroll
        for (int kk = 0; kk < 8; kk++) {
#pragma unroll
            for (int n = 0; n < 8; n++) {
                int key = n*8 + r1;
                uint2 b2 = *(const uint2*)&Kp[key*KP_ST + kk*8 + 2*q];
                uint32_t bfr[2] = {b2.x, b2.y};
                mma_tf32(sf[n], qf[kk], bfr);
            }
        }

        // causal mask on diagonal tile
        if (kt == qt) {
#pragma unroll
            for (int n = 0; n < 8; n++) {
                int col = n*8 + 2*q;
                if (col     > qrow)     sf[n][0] = -1e30f;
                if (col + 1 > qrow)     sf[n][1] = -1e30f;
                if (col     > qrow + 8) sf[n][2] = -1e30f;
                if (col + 1 > qrow + 8) sf[n][3] = -1e30f;
            }
        }

        // online softmax
        float mx1 = -1e30f, mx2 = -1e30f;
#pragma unroll
        for (int n = 0; n < 8; n++) {
            mx1 = fmaxf(mx1, fmaxf(sf[n][0], sf[n][1]));
            mx2 = fmaxf(mx2, fmaxf(sf[n][2], sf[n][3]));
        }
        mx1 = fmaxf(mx1, __shfl_xor_sync(0xffffffffu, mx1, 1));
        mx1 = fmaxf(mx1, __shfl_xor_sync(0xffffffffu, mx1, 2));
        mx2 = fmaxf(mx2, __shfl_xor_sync(0xffffffffu, mx2, 1));
        mx2 = fmaxf(mx2, __shfl_xor_sync(0xffffffffu, mx2, 2));
        float mn1 = fmaxf(m1, mx1), mn2 = fmaxf(m2, mx2);
        float c1 = __expf(m1 - mn1), c2 = __expf(m2 - mn2);
        float s1 = 0.0f, s2 = 0.0f;
#pragma unroll
        for (int n = 0; n < 8; n++) {
            sf[n][0] = __expf(sf[n][0] - mn1);
            sf[n][1] = __expf(sf[n][1] - mn1);
            sf[n][2] = __expf(sf[n][2] - mn2);
            sf[n][3] = __expf(sf[n][3] - mn2);
            s1 += sf[n][0] + sf[n][1];
            s2 += sf[n][2] + sf[n][3];
        }
        s1 += __shfl_xor_sync(0xffffffffu, s1, 1);
        s1 += __shfl_xor_sync(0xffffffffu, s1, 2);
        s2 += __shfl_xor_sync(0xffffffffu, s2, 1);
        s2 += __shfl_xor_sync(0xffffffffu, s2, 2);
        l1 = l1*c1 + s1;  l2 = l2*c2 + s2;
        m1 = mn1;         m2 = mn2;
#pragma unroll
        for (int n = 0; n < 8; n++) {
            of[n][0] *= c1; of[n][1] *= c1;
            of[n][2] *= c2; of[n][3] *= c2;
        }

        // P -> tf32 (same cvt point)
        uint32_t pt[8][4];
#pragma unroll
        for (int n = 0; n < 8; n++) {
            pt[n][0] = f2tf(sf[n][0]);
            pt[n][1] = f2tf(sf[n][1]);
            pt[n][2] = f2tf(sf[n][2]);
            pt[n][3] = f2tf(sf[n][3]);
        }

        // O += P V ; A-frag of P via in-quad shuffles, V-frag = 1 LDS.64 (CF)
#pragma unroll
        for (int kk = 0; kk < 8; kk++) {
            uint32_t v00 = __shfl_sync(0xffffffffu, pt[kk][0], srcA);
            uint32_t v01 = __shfl_sync(0xffffffffu, pt[kk][1], srcA);
            uint32_t v10 = __shfl_sync(0xffffffffu, pt[kk][2], srcA);
            uint32_t v11 = __shfl_sync(0xffffffffu, pt[kk][3], srcA);
            uint32_t v20 = __shfl_sync(0xffffffffu, pt[kk][0], srcB);
            uint32_t v21 = __shfl_sync(0xffffffffu, pt[kk][1], srcB);
            uint32_t v30 = __shfl_sync(0xffffffffu, pt[kk][2], srcB);
            uint32_t v31 = __shfl_sync(0xffffffffu, pt[kk][3], srcB);
            uint32_t pa[4];
            pa[0] = qodd ? v01 : v00;   // P[r1  ][kk*8+q]
            pa[1] = qodd ? v11 : v10;   // P[r1+8][kk*8+q]
            pa[2] = qodd ? v21 : v20;   // P[r1  ][kk*8+q+4]
            pa[3] = qodd ? v31 : v30;   // P[r1+8][kk*8+q+4]
            int slot = kk*4 + q;
#pragma unroll
            for (int n = 0; n < 8; n++) {
                uint2 v2 = *(const uint2*)&Vp[slot*VP_ST + (n*8 + r1)*2];
                uint32_t vb[2] = {v2.x, v2.y};
                mma_tf32(of[n], pa, vb);
            }
        }

        // next stage: own copies done + barrier makes all threads' copies visible
        if (kt < qt) CP_WAIT0();
        __syncthreads();
    }

    float inv1 = 1.0f / l1, inv2 = 1.0f / l2;
    float* Ob = g_attn + (size_t)b*SS*DMODEL + h*DK;
#pragma unroll
    for (int n = 0; n < 8; n++) {
        int col = n*8 + 2*q;
        float2 v0 = {of[n][0]*inv1, of[n][1]*inv1};
        *(float2*)&Ob[(size_t)(q0 + qrow)*DMODEL + col] = v0;
        float2 v1 = {of[n][2]*inv2, of[n][3]*inv2};
        *(float2*)&Ob[(size_t)(q0 + qrow + 8)*DMODEL + col] = v1;
    }
}

// ---------------- launch ----------------
extern "C" void kernel_launch(void* const* d_in, const int* in_sizes, int n_in,
                              void* d_out, int out_size) {
    const float* x  = (const float*)d_in[0];
    const float* wq = (const float*)d_in[1];
    const float* bq = (const float*)d_in[2];
    const float* wk = (const float*)d_in[3];
    const float* bk = (const float*)d_in[4];
    const float* wv = (const float*)d_in[5];
    const float* bv = (const float*)d_in[6];
    const float* wo = (const float*)d_in[7];
    const float* bo = (const float*)d_in[8];
    float* out = (float*)d_out;

    float *A, *cT, *sT;
    cudaGetSymbolAddress((void**)&A,  g_attn);
    cudaGetSymbolAddress((void**)&cT, g_cos);
    cudaGetSymbolAddress((void**)&sT, g_sin);

    static int cfg_done = 0;
    if (!cfg_done) {
        cudaFuncSetAttribute(attn_tf32, cudaFuncAttributeMaxDynamicSharedMemorySize, ATT_SMEM);
        cfg_done = 1;
    }

    // RoPE tables
    freq_rope_kernel<<<(SS*(DK/2) + 255)/256, 256>>>(cT, sT);

    // fused Q+K+V projections (one launch)
    gemm_qkv<<<384, 256>>>(x, wq, bq, wk, bk, wv, bv);

    // RoPE applied in-place on Q and K
    {
        int total = BB*SS*HQ*(DK/2) + BB*SS*HKV*(DK/2);
        rope_kernel<<<(total + 255)/256, 256>>>();
    }

    // pre-convert K/V to tf32 tile-interleaved layouts
    prep_kv<<<(2*256*4096)/256, 256>>>();

    // attention (2 heads per CTA share K/V)
    attn_tf32<<<dim3(SS/64, BB*HKV*2), 256, ATT_SMEM>>>();

    // output projection
    gemm_o<<<dim3(DMODEL/128, BB*SS/128), 256>>>(A, wo, bo, out);
}